// round 2
// baseline (speedup 1.0000x reference)
#include <cuda_runtime.h>

// SSIM loss, fused single pass.
// pred/target: (16,3,512,512) fp32. out: 16 fp32 (1 - mean ssim per sample).
//
// 11x11 box filter (zero-padded, /121 always) done separably:
//   horizontal: 11-tap window from shared row buffer (4 px per thread, sliding)
//   vertical:   running sums + 11-deep ring buffer of horizontal sums in smem
// Grid: 48 images x 3 row strips = 144 blocks (1 wave). 128 threads x 4 cols = 512 wide.

#define WIDTH   512
#define HEIGHT  512
#define WIN     11
#define PADR    5
#define NT      128
#define NSTRIP  3
#define STRIPH  171
#define RS      528            // padded row-buffer stride (floats), 16B-multiple
#define NIMG    48
#define NBLOCKS (NIMG * NSTRIP)

__device__ float g_partials[NBLOCKS];

__global__ __launch_bounds__(NT, 1)
void ssim_main_kernel(const float* __restrict__ pred, const float* __restrict__ targ) {
    extern __shared__ float sm[];
    // ring: [11 slots][5 quantities][NT] of float4 (per-thread private slots)
    float4* ring = reinterpret_cast<float4*>(sm);
    float* prow = sm + 55 * NT * 4;     // [2][RS]
    float* trow = prow + 2 * RS;        // [2][RS]
    float* red  = trow + 2 * RS;        // [NT]

    const int tid   = threadIdx.x;
    const int bid   = blockIdx.x;
    const int img   = bid / NSTRIP;
    const int strip = bid - img * NSTRIP;
    const int r0    = strip * STRIPH;
    const int r1    = min(HEIGHT, r0 + STRIPH);

    const float* __restrict__ P = pred + (size_t)img * (WIDTH * HEIGHT);
    const float* __restrict__ T = targ + (size_t)img * (WIDTH * HEIGHT);
    const int x0 = tid * 4;

    const float4 z4 = make_float4(0.f, 0.f, 0.f, 0.f);
    // zero ring (each thread owns its slots; no cross-thread use)
    #pragma unroll
    for (int i = 0; i < 55; i++) ring[i * NT + tid] = z4;

    // zero pads of both row buffers. Mapping: image x stored at buf[x+8].
    // left zeros: x=-5..-1 -> idx 3..7 ; right zeros: x=512..516 -> idx 520..524
    if (tid < 2 * PADR) {
        int k = (tid < PADR) ? (3 + tid) : (520 + (tid - PADR));
        prow[k] = 0.f; prow[RS + k] = 0.f;
        trow[k] = 0.f; trow[RS + k] = 0.f;
    }

    float S[5][4];
    #pragma unroll
    for (int q = 0; q < 5; q++)
        #pragma unroll
        for (int j = 0; j < 4; j++) S[q][j] = 0.f;

    float acc = 0.f;

    int yin = r0 - PADR;
    float4 cp = z4, ct = z4;
    if (yin >= 0) {
        cp = *(const float4*)(P + yin * WIDTH + x0);
        ct = *(const float4*)(T + yin * WIDTH + x0);
    }
    int slot = 0;

    __syncthreads();   // pads visible before first horizontal pass

    const int yend = r1 + PADR;
    for (; yin < yend; ++yin) {
        const int buf = yin & 1;
        float* pr = prow + buf * RS;
        float* tr = trow + buf * RS;
        const bool valid = (yin >= 0) && (yin < HEIGHT);
        if (valid) {
            *(float4*)(pr + x0 + 8) = cp;
            *(float4*)(tr + x0 + 8) = ct;
        }
        // prefetch next row (latency hidden behind this row's compute)
        const int yn = yin + 1;
        if (yn >= 0 && yn < HEIGHT) {
            cp = *(const float4*)(P + yn * WIDTH + x0);
            ct = *(const float4*)(T + yn * WIDTH + x0);
        }
        __syncthreads();   // double-buffered rows: one bar/row is sufficient

        float Hh[5][4];
        if (valid) {
            // window for outputs x0..x0+3 covers x in [x0-5, x0+8] -> idx [x0+3, x0+16]
            float pv[14], tv[14];
            {
                float  a0 = pr[x0 + 3];
                float4 a1 = *(const float4*)(pr + x0 + 4);
                float4 a2 = *(const float4*)(pr + x0 + 8);
                float4 a3 = *(const float4*)(pr + x0 + 12);
                float  a4 = pr[x0 + 16];
                pv[0]=a0;   pv[1]=a1.x; pv[2]=a1.y; pv[3]=a1.z; pv[4]=a1.w;
                pv[5]=a2.x; pv[6]=a2.y; pv[7]=a2.z; pv[8]=a2.w;
                pv[9]=a3.x; pv[10]=a3.y; pv[11]=a3.z; pv[12]=a3.w;
                pv[13]=a4;
            }
            {
                float  b0 = tr[x0 + 3];
                float4 b1 = *(const float4*)(tr + x0 + 4);
                float4 b2 = *(const float4*)(tr + x0 + 8);
                float4 b3 = *(const float4*)(tr + x0 + 12);
                float  b4 = tr[x0 + 16];
                tv[0]=b0;   tv[1]=b1.x; tv[2]=b1.y; tv[3]=b1.z; tv[4]=b1.w;
                tv[5]=b2.x; tv[6]=b2.y; tv[7]=b2.z; tv[8]=b2.w;
                tv[9]=b3.x; tv[10]=b3.y; tv[11]=b3.z; tv[12]=b3.w;
                tv[13]=b4;
            }
            float hp=0.f, ht=0.f, hpp=0.f, htt=0.f, hpt=0.f;
            #pragma unroll
            for (int k = 0; k < 11; k++) {
                hp += pv[k]; ht += tv[k];
                hpp = fmaf(pv[k], pv[k], hpp);
                htt = fmaf(tv[k], tv[k], htt);
                hpt = fmaf(pv[k], tv[k], hpt);
            }
            Hh[0][0]=hp; Hh[1][0]=ht; Hh[2][0]=hpp; Hh[3][0]=htt; Hh[4][0]=hpt;
            #pragma unroll
            for (int j = 1; j < 4; j++) {
                const float pn = pv[j+10], po = pv[j-1];
                const float tn = tv[j+10], to = tv[j-1];
                hp += pn - po;
                ht += tn - to;
                hpp = fmaf(pn, pn, hpp); hpp = fmaf(-po, po, hpp);
                htt = fmaf(tn, tn, htt); htt = fmaf(-to, to, htt);
                hpt = fmaf(pn, tn, hpt); hpt = fmaf(-po, to, hpt);
                Hh[0][j]=hp; Hh[1][j]=ht; Hh[2][j]=hpp; Hh[3][j]=htt; Hh[4][j]=hpt;
            }
        } else {
            #pragma unroll
            for (int q = 0; q < 5; q++)
                #pragma unroll
                for (int j = 0; j < 4; j++) Hh[q][j] = 0.f;
        }

        // vertical sliding sums via per-thread ring in shared (float4, conflict-free)
        #pragma unroll
        for (int q = 0; q < 5; q++) {
            float4* sp = ring + (slot * 5 + q) * NT + tid;
            const float4 old = *sp;
            S[q][0] += Hh[q][0] - old.x;
            S[q][1] += Hh[q][1] - old.y;
            S[q][2] += Hh[q][2] - old.z;
            S[q][3] += Hh[q][3] - old.w;
            *sp = make_float4(Hh[q][0], Hh[q][1], Hh[q][2], Hh[q][3]);
        }
        slot = (slot == WIN - 1) ? 0 : slot + 1;

        // emit output row r = yin - 5 once full window accumulated
        if (yin >= r0 + PADR) {
            const float inv = 1.f / 121.f;
            const float c1 = 1e-4f, c2 = 9e-4f;
            #pragma unroll
            for (int j = 0; j < 4; j++) {
                const float m1  = S[0][j] * inv;
                const float m2  = S[1][j] * inv;
                const float ex  = S[2][j] * inv;
                const float ey  = S[3][j] * inv;
                const float exy = S[4][j] * inv;
                const float m12 = m1 * m2;
                const float num = fmaf(2.f, m12, c1) * fmaf(2.f, exy - m12, c2);
                const float den = (fmaf(m1, m1, m2 * m2) + c1)
                                * ((ex - m1 * m1) + (ey - m2 * m2) + c2);
                acc += __saturatef(__fdividef(num, den));
            }
        }
    }

    // deterministic block reduction
    red[tid] = acc;
    __syncthreads();
    #pragma unroll
    for (int s = NT / 2; s > 0; s >>= 1) {
        if (tid < s) red[tid] += red[tid + s];
        __syncthreads();
    }
    if (tid == 0) g_partials[bid] = red[0];
}

__global__ void ssim_finalize_kernel(float* __restrict__ out) {
    const int i = threadIdx.x;
    if (i < 16) {
        float s = 0.f;
        // 3 channels * NSTRIP strips = 9 partials per sample
        #pragma unroll
        for (int j = 0; j < 3 * NSTRIP; j++) s += g_partials[i * (3 * NSTRIP) + j];
        out[i] = 1.f - s * (1.f / (3.f * 512.f * 512.f));
    }
}

extern "C" void kernel_launch(void* const* d_in, const int* in_sizes, int n_in,
                              void* d_out, int out_size) {
    const float* pred = (const float*)d_in[0];
    const float* targ = (const float*)d_in[1];
    const int smem = (55 * NT * 4 + 4 * RS + NT) * sizeof(float);   // 121600 B
    cudaFuncSetAttribute(ssim_main_kernel,
                         cudaFuncAttributeMaxDynamicSharedMemorySize, smem);
    ssim_main_kernel<<<NBLOCKS, NT, smem>>>(pred, targ);
    ssim_finalize_kernel<<<1, 32>>>((float*)d_out);
}